// round 15
// baseline (speedup 1.0000x reference)
#include <cuda_runtime.h>
#include <cuda_fp16.h>
#include <math.h>
#include <stdint.h>

#define T_TOK 2048
#define HID   2048
#define INTD  1024
#define NE    32
#define NE_TOT 33
#define TOPK  4
#define MAXTILES 112
#define BM    128
#define ROWS_MAX 10368

// ===================== device scratch =====================
__device__ int   g_cnt[NE_TOT];
__device__ int   g_tok[NE_TOT * T_TOK];
__device__ float g_w  [NE_TOT * T_TOK];
__device__ int   g_off[NE_TOT + 1];
__device__ int   g_tile_e[MAXTILES];
__device__ int   g_tile_s[MAXTILES];
__device__ int   g_ntiles;
// x as single fp16 plane (written by router)
__device__ __align__(16) __half g_xhi[(size_t)T_TOK * HID];
// intermediate h = silu(g)*u, single fp16 plane
__device__ __align__(16) __half g_hhi[(size_t)ROWS_MAX * INTD];

// ===================== PTX helpers =====================
__device__ __forceinline__ uint32_t smem_u32(const void* p) {
    uint32_t a;
    asm("{ .reg .u64 t; cvta.to.shared.u64 t, %1; cvt.u32.u64 %0, t; }" : "=r"(a) : "l"(p));
    return a;
}
__device__ __forceinline__ void ldsm_x4(uint32_t* r, uint32_t a) {
    asm volatile("ldmatrix.sync.aligned.m8n8.x4.shared.b16 {%0,%1,%2,%3}, [%4];"
                 : "=r"(r[0]), "=r"(r[1]), "=r"(r[2]), "=r"(r[3]) : "r"(a));
}
__device__ __forceinline__ void ldsm_x4_t(uint32_t* r, uint32_t a) {
    asm volatile("ldmatrix.sync.aligned.m8n8.x4.trans.shared.b16 {%0,%1,%2,%3}, [%4];"
                 : "=r"(r[0]), "=r"(r[1]), "=r"(r[2]), "=r"(r[3]) : "r"(a));
}
__device__ __forceinline__ void mma_f16(float* c, const uint32_t* a, const uint32_t* b) {
    asm volatile("mma.sync.aligned.m16n8k16.row.col.f32.f16.f16.f32 "
        "{%0,%1,%2,%3}, {%4,%5,%6,%7}, {%8,%9}, {%0,%1,%2,%3};"
        : "+f"(c[0]), "+f"(c[1]), "+f"(c[2]), "+f"(c[3])
        : "r"(a[0]), "r"(a[1]), "r"(a[2]), "r"(a[3]), "r"(b[0]), "r"(b[1]));
}
__device__ __forceinline__ uint2 cvt4h(float4 f) {
    __half2 h01 = __floats2half2_rn(f.x, f.y);
    __half2 h23 = __floats2half2_rn(f.z, f.w);
    return make_uint2(*(uint32_t*)&h01, *(uint32_t*)&h23);
}
#define CP_ASYNC16(dst, src) \
    asm volatile("cp.async.cg.shared.global [%0], [%1], 16;" \
                 :: "r"((uint32_t)(dst)), "l"(src))
#define CP_COMMIT() asm volatile("cp.async.commit_group;" ::: "memory")
#define CP_WAIT0()  asm volatile("cp.async.wait_group 0;" ::: "memory")

// ===================== small kernels =====================
__global__ void zero_kernel() {
    int t = threadIdx.x;
    if (t < NE) g_cnt[t] = 0;
    if (t == NE) g_cnt[NE] = T_TOK;
}

// router v2 + x->fp16 plane (fused). 64 blocks x 256 thr; each warp: 4 tokens.
__global__ void __launch_bounds__(256)
router_kernel(const float* __restrict__ x,
              const float* __restrict__ rw,
              const float* __restrict__ bias) {
    __shared__ float rwS[32][65];
    __shared__ float xS[32][64];   // 32 tokens x 64-h chunk
    int tid = threadIdx.x;
    int warp = tid >> 5, lane = tid & 31;
    int t0 = blockIdx.x * 32;      // 32 tokens per block

    float acc[4] = {0.f, 0.f, 0.f, 0.f};
    int xr = tid >> 3, xc = (tid & 7) * 8;   // per-thread x slice: token row, 8 cols

    for (int h0 = 0; h0 < HID; h0 += 64) {
        __syncthreads();
        // rw chunk: 32 experts x 64
        for (int i = tid; i < 32 * 64; i += 256) {
            int e = i >> 6, j = i & 63;
            rwS[e][j] = rw[e * HID + h0 + j];
        }
        // x chunk: 32 tokens x 64 (8 floats per thread) + fused fp16 plane write
        {
            size_t go = (size_t)(t0 + xr) * HID + h0 + xc;
            float4 a = *(const float4*)&x[go];
            float4 b = *(const float4*)&x[go + 4];
            *(float4*)&xS[xr][xc]     = a;
            *(float4*)&xS[xr][xc + 4] = b;
            *(uint2*)&g_xhi[go]     = cvt4h(a);
            *(uint2*)&g_xhi[go + 4] = cvt4h(b);
        }
        __syncthreads();
        #pragma unroll
        for (int tt = 0; tt < 4; tt++) {
            int row = warp * 4 + tt;
            float a = acc[tt];
            #pragma unroll 8
            for (int j = 0; j < 64; j++)
                a += xS[row][j] * rwS[lane][j];
            acc[tt] = a;
        }
    }

    // top-4 per token (4 tokens per warp, sequential)
    #pragma unroll
    for (int tt = 0; tt < 4; tt++) {
        int t = t0 + warp * 4 + tt;
        float score = 1.f / (1.f + __expf(-acc[tt]));
        float selv  = score + bias[lane];

        int   picks[TOPK];
        float pw[TOPK];
        float wsum = 0.f;
        #pragma unroll
        for (int k = 0; k < TOPK; k++) {
            float v = selv; int idx = lane;
            #pragma unroll
            for (int o = 16; o > 0; o >>= 1) {
                float v2 = __shfl_xor_sync(0xFFFFFFFFu, v, o);
                int   i2 = __shfl_xor_sync(0xFFFFFFFFu, idx, o);
                if (v2 > v || (v2 == v && i2 < idx)) { v = v2; idx = i2; }
            }
            picks[k] = idx;
            float w = __shfl_sync(0xFFFFFFFFu, score, idx);
            pw[k] = w; wsum += w;
            if (lane == idx) selv = -INFINITY;
        }
        if (lane == 0) {
            float inv = 1.f / (wsum + 1e-20f);
            #pragma unroll
            for (int k = 0; k < TOPK; k++) {
                int e = picks[k];
                int pos = atomicAdd(&g_cnt[e], 1);
                g_tok[e * T_TOK + pos] = t;
                g_w  [e * T_TOK + pos] = pw[k] * inv;
            }
            g_tok[NE * T_TOK + t] = t;
            g_w  [NE * T_TOK + t] = 1.0f;
        }
    }
}

__global__ void build_tiles_kernel() {
    if (threadIdx.x == 0 && blockIdx.x == 0) {
        int off = 0, nt = 0;
        for (int e = 0; e < NE_TOT; e++) {
            g_off[e] = off;
            int c = g_cnt[e];
            for (int s = 0; s < c && nt < MAXTILES; s += BM) {
                g_tile_e[nt] = e; g_tile_s[nt] = s; nt++;
            }
            off += c;
        }
        g_off[NE_TOT] = off;
        g_ntiles = nt;
    }
}

// ===================== gate+up GEMM, fp16 single-pass, occ 2 =====================
// CTA: M128 x N64 (gate AND up). A via cp.async (fp16 plane); B inline LDG->cvt->STS
// (latency covered by sibling CTA). stage 32KB: A 16KB ; Bg 8KB | Bu 8KB.
#define GU_SMEM (1024 + 2 * 32768)
__global__ void __launch_bounds__(256, 2)
gu_gemm(const float* __restrict__ wgR, const float* __restrict__ wuR,
        const float* __restrict__ wgS, const float* __restrict__ wuS) {
    extern __shared__ char sm[];
    uint32_t sa = smem_u32(sm);
    int* rowTokS = (int*)sm;

    int tilei = blockIdx.y;
    if (tilei >= g_ntiles) return;
    int e = g_tile_e[tilei], s0 = g_tile_s[tilei];
    int rows = min(BM, g_cnt[e] - s0);
    int hidbase = g_off[e] + s0;
    int N0 = blockIdx.x * 64;

    int tid = threadIdx.x, lane = tid & 31, wid = tid >> 5;
    int wm = wid & 3, wn = wid >> 2;

    if (tid < 128)
        rowTokS[tid] = g_tok[e * T_TOK + s0 + min(tid, rows - 1)];
    __syncthreads();

    const float* gptr = (e < NE) ? wgR + (size_t)e * HID * INTD : wgS;
    const float* uptr = (e < NE) ? wuR + (size_t)e * HID * INTD : wuS;

    // A: rows (tid>>3)+32i (i<4), granule aJ=tid&7 (16B)
    int aJ = tid & 7;
    int tokR[4];
    uint32_t aDst[4];
    #pragma unroll
    for (int i = 0; i < 4; i++) {
        int r = (tid >> 3) + 32 * i;
        tokR[i] = rowTokS[r];
        aDst[i] = r * 128 + ((aJ * 16) ^ ((r & 7) << 4));
    }
    // B: each matrix 64k x 64n fp32; per thread row bK=tid>>2, cols bC+16j (j<4)
    int bK = tid >> 2, bC = (tid & 3) * 4;

    // prologue: cp.async A(0) -> buf0
    {
        uint32_t As0 = sa + 1024;
        #pragma unroll
        for (int i = 0; i < 4; i++)
            CP_ASYNC16(As0 + aDst[i], &g_xhi[(size_t)tokR[i] * HID + aJ * 8]);
        CP_COMMIT();
    }

    float accG[2][4][4], accU[2][4][4];
    #pragma unroll
    for (int a = 0; a < 2; a++)
        #pragma unroll
        for (int b = 0; b < 4; b++)
            #pragma unroll
            for (int f = 0; f < 4; f++) { accG[a][b][f] = 0.f; accU[a][b][f] = 0.f; }

    const int KCH = HID / 64;
    int lm = lane & 15, lkh = lane >> 4;
    int swb = (bK & 7) << 4;

    for (int c = 0; c < KCH; c++) {
        uint32_t As = sa + 1024 + (c & 1) * 32768;
        uint32_t Bg = As + 16384;
        char* Bsm = sm + 1024 + (c & 1) * 32768 + 16384;
        int k0 = c * 64;

        CP_WAIT0();
        // inline B(c): LDG fp32 -> cvt -> STS (exposed latency; sibling CTA covers)
        #pragma unroll
        for (int j = 0; j < 4; j++) {
            float4 g4 = *(const float4*)&gptr[(size_t)(k0 + bK) * INTD + N0 + bC + 16 * j];
            float4 u4 = *(const float4*)&uptr[(size_t)(k0 + bK) * INTD + N0 + bC + 16 * j];
            int nb = (bC + 16 * j) * 2;
            *(uint2*)(Bsm +        bK * 128 + (nb ^ swb)) = cvt4h(g4);
            *(uint2*)(Bsm + 8192 + bK * 128 + (nb ^ swb)) = cvt4h(u4);
        }
        __syncthreads();

        if (c + 1 < KCH) {
            int kn = (c + 1) * 64;
            uint32_t Asn = sa + 1024 + ((c + 1) & 1) * 32768;
            #pragma unroll
            for (int i = 0; i < 4; i++)
                CP_ASYNC16(Asn + aDst[i], &g_xhi[(size_t)tokR[i] * HID + kn + aJ * 8]);
            CP_COMMIT();
        }

        #pragma unroll
        for (int ks = 0; ks < 4; ks++) {
            uint32_t Gh[2][4], Uh[2][4];
            #pragma unroll
            for (int pr = 0; pr < 2; pr++) {
                int k = ks * 16 + lm;
                int n = wn * 32 + pr * 16 + lkh * 8;
                uint32_t ad = Bg + k * 128 + ((n * 2) ^ ((k & 7) << 4));
                ldsm_x4_t(Gh[pr], ad);
                ldsm_x4_t(Uh[pr], ad + 8192);
            }
            #pragma unroll
            for (int mt = 0; mt < 2; mt++) {
                int m = wm * 32 + mt * 16 + lm;
                int boff = (lkh * 16 + ks * 32) ^ ((m & 7) << 4);
                uint32_t Ah[4];
                ldsm_x4(Ah, As + m * 128 + boff);
                #pragma unroll
                for (int nt = 0; nt < 4; nt++) {
                    mma_f16(accG[mt][nt], Ah, &Gh[nt >> 1][(nt & 1) * 2]);
                    mma_f16(accU[mt][nt], Ah, &Uh[nt >> 1][(nt & 1) * 2]);
                }
            }
        }
    }

    // epilogue: fuse locally, write single fp16 plane
    int gr = lane >> 2, gc = (lane & 3) * 2;
    #pragma unroll
    for (int mt = 0; mt < 2; mt++) {
        #pragma unroll
        for (int nt = 0; nt < 4; nt++) {
            int col = N0 + wn * 32 + nt * 8 + gc;
            #pragma unroll
            for (int p = 0; p < 2; p++) {
                int r = wm * 32 + mt * 16 + gr + p * 8;
                if (r < rows) {
                    float g0 = accG[mt][nt][2 * p], g1 = accG[mt][nt][2 * p + 1];
                    float u0 = accU[mt][nt][2 * p], u1 = accU[mt][nt][2 * p + 1];
                    float h0 = (g0 / (1.f + __expf(-g0))) * u0;
                    float h1 = (g1 / (1.f + __expf(-g1))) * u1;
                    __half2 hh(__float2half_rn(h0), __float2half_rn(h1));
                    size_t o = (size_t)(hidbase + r) * INTD + col;
                    *(uint32_t*)&g_hhi[o] = *(uint32_t*)&hh;
                }
            }
        }
    }
}

// ===================== down GEMM, fp16 single-pass, occ 2 + scatter =====================
// CTA: M128 x N128. A via cp.async; B inline LDG->cvt->STS.
// stage 32KB: A 16KB ; B 16KB (64k x 128n fp16, 256B rows).
#define DN_SMEM (1024 + 2 * 32768)
__global__ void __launch_bounds__(256, 2)
dn_gemm(const float* __restrict__ wdR, const float* __restrict__ wdS,
        float* __restrict__ out) {
    extern __shared__ char sm[];
    uint32_t sa = smem_u32(sm);
    int* rowTokS = (int*)sm;
    float* rowWS = (float*)(sm + 512);

    int tilei = blockIdx.y;
    if (tilei >= g_ntiles) return;
    int e = g_tile_e[tilei], s0 = g_tile_s[tilei];
    int rows = min(BM, g_cnt[e] - s0);
    int hidbase = g_off[e] + s0;
    int N0 = blockIdx.x * 128;

    int tid = threadIdx.x, lane = tid & 31, wid = tid >> 5;
    int wm = wid & 3, wn = wid >> 2;

    if (tid < 128) {
        int idx = e * T_TOK + s0 + min(tid, rows - 1);
        rowTokS[tid] = g_tok[idx];
        rowWS[tid]   = g_w[idx];
    }
    __syncthreads();

    const float* wd = (e < NE) ? wdR + (size_t)e * INTD * HID : wdS;

    int aJ = tid & 7;
    int arR[4];
    uint32_t aDst[4];
    #pragma unroll
    for (int i = 0; i < 4; i++) {
        int r = (tid >> 3) + 32 * i;
        arR[i] = hidbase + min(r, rows - 1);
        aDst[i] = r * 128 + ((aJ * 16) ^ ((r & 7) << 4));
    }
    int bK = tid >> 2, bC = (tid & 3) * 4;

    {
        uint32_t As0 = sa + 1024;
        #pragma unroll
        for (int i = 0; i < 4; i++)
            CP_ASYNC16(As0 + aDst[i], &g_hhi[(size_t)arR[i] * INTD + aJ * 8]);
        CP_COMMIT();
    }

    float acc[2][8][4];
    #pragma unroll
    for (int a = 0; a < 2; a++)
        #pragma unroll
        for (int b = 0; b < 8; b++)
            #pragma unroll
            for (int f = 0; f < 4; f++) acc[a][b][f] = 0.f;

    const int KCH = INTD / 64;
    int lm = lane & 15, lkh = lane >> 4;
    int swb = (bK & 7) << 4;

    for (int c = 0; c < KCH; c++) {
        uint32_t As = sa + 1024 + (c & 1) * 32768;
        uint32_t Bs = As + 16384;
        char* Bsm = sm + 1024 + (c & 1) * 32768 + 16384;
        int k0 = c * 64;

        CP_WAIT0();
        #pragma unroll
        for (int j = 0; j < 8; j++) {
            float4 b4 = *(const float4*)&wd[(size_t)(k0 + bK) * HID + N0 + bC + 16 * j];
            int nb = (bC + 16 * j) * 2;
            *(uint2*)(Bsm + bK * 256 + (nb ^ swb)) = cvt4h(b4);
        }
        __syncthreads();

        if (c + 1 < KCH) {
            int kn = (c + 1) * 64;
            uint32_t Asn = sa + 1024 + ((c + 1) & 1) * 32768;
            #pragma unroll
            for (int i = 0; i < 4; i++)
                CP_ASYNC16(Asn + aDst[i], &g_hhi[(size_t)arR[i] * INTD + kn + aJ * 8]);
            CP_COMMIT();
        }

        #pragma unroll
        for (int ks = 0; ks < 4; ks++) {
            uint32_t Bh[4][4];
            #pragma unroll
            for (int h = 0; h < 2; h++)
                #pragma unroll
                for (int pr = 0; pr < 2; pr++) {
                    int k = ks * 16 + lm;
                    int n = wn * 64 + h * 32 + pr * 16 + lkh * 8;
                    uint32_t ad = Bs + k * 256 + ((n * 2) ^ ((k & 7) << 4));
                    ldsm_x4_t(Bh[h * 2 + pr], ad);
                }
            #pragma unroll
            for (int mt = 0; mt < 2; mt++) {
                int m = wm * 32 + mt * 16 + lm;
                int boff = (lkh * 16 + ks * 32) ^ ((m & 7) << 4);
                uint32_t Ah[4];
                ldsm_x4(Ah, As + m * 128 + boff);
                #pragma unroll
                for (int nt = 0; nt < 8; nt++)
                    mma_f16(acc[mt][nt], Ah, &Bh[nt >> 1][(nt & 1) * 2]);
            }
        }
    }

    int gr = lane >> 2, gc = (lane & 3) * 2;
    #pragma unroll
    for (int mt = 0; mt < 2; mt++) {
        #pragma unroll
        for (int nt = 0; nt < 8; nt++) {
            int r0 = wm * 32 + mt * 16 + gr;
            int col = N0 + wn * 64 + nt * 8 + gc;
            if (r0 < rows) {
                int tok = rowTokS[r0]; float w = rowWS[r0];
                atomicAdd(&out[(size_t)tok * HID + col],     acc[mt][nt][0] * w);
                atomicAdd(&out[(size_t)tok * HID + col + 1], acc[mt][nt][1] * w);
            }
            if (r0 + 8 < rows) {
                int tok = rowTokS[r0 + 8]; float w = rowWS[r0 + 8];
                atomicAdd(&out[(size_t)tok * HID + col],     acc[mt][nt][2] * w);
                atomicAdd(&out[(size_t)tok * HID + col + 1], acc[mt][nt][3] * w);
            }
        }
    }
}

// ===================== launch =====================
extern "C" void kernel_launch(void* const* d_in, const int* in_sizes, int n_in,
                              void* d_out, int out_size) {
    const float* x    = (const float*)d_in[0];
    const float* rw   = (const float*)d_in[1];
    const float* bias = (const float*)d_in[2];
    const float* wg   = (const float*)d_in[3];
    const float* wu   = (const float*)d_in[4];
    const float* wd   = (const float*)d_in[5];
    const float* swg  = (const float*)d_in[6];
    const float* swu  = (const float*)d_in[7];
    const float* swd  = (const float*)d_in[8];
    float* out = (float*)d_out;

    cudaFuncSetAttribute(gu_gemm, cudaFuncAttributeMaxDynamicSharedMemorySize, GU_SMEM);
    cudaFuncSetAttribute(dn_gemm, cudaFuncAttributeMaxDynamicSharedMemorySize, DN_SMEM);

    cudaMemsetAsync(d_out, 0, (size_t)out_size * sizeof(float));
    zero_kernel<<<1, 64>>>();
    router_kernel<<<T_TOK / 32, 256>>>(x, rw, bias);
    build_tiles_kernel<<<1, 32>>>();

    gu_gemm<<<dim3(INTD / 64, MAXTILES), 256, GU_SMEM>>>(wg, wu, swg, swu);
    dn_gemm<<<dim3(HID / 128, MAXTILES), 256, DN_SMEM>>>(wd, swd, out);
}

// round 16
// speedup vs baseline: 1.0388x; 1.0388x over previous
#include <cuda_runtime.h>
#include <cuda_fp16.h>
#include <math.h>
#include <stdint.h>

#define T_TOK 2048
#define HID   2048
#define INTD  1024
#define NE    32
#define NE_TOT 33
#define TOPK  4
#define MAXTILES 112
#define BM    128
#define ROWS_MAX 10368

// ===================== device scratch =====================
__device__ int   g_cnt[NE];            // routed expert counters (memset to 0)
__device__ int   g_tok[NE_TOT * T_TOK];
__device__ float g_w  [NE_TOT * T_TOK];
// x as single fp16 plane (written by router)
__device__ __align__(16) __half g_xhi[(size_t)T_TOK * HID];
// intermediate h = silu(g)*u, single fp16 plane
__device__ __align__(16) __half g_hhi[(size_t)ROWS_MAX * INTD];

// ===================== PTX helpers =====================
__device__ __forceinline__ uint32_t smem_u32(const void* p) {
    uint32_t a;
    asm("{ .reg .u64 t; cvta.to.shared.u64 t, %1; cvt.u32.u64 %0, t; }" : "=r"(a) : "l"(p));
    return a;
}
__device__ __forceinline__ void ldsm_x4(uint32_t* r, uint32_t a) {
    asm volatile("ldmatrix.sync.aligned.m8n8.x4.shared.b16 {%0,%1,%2,%3}, [%4];"
                 : "=r"(r[0]), "=r"(r[1]), "=r"(r[2]), "=r"(r[3]) : "r"(a));
}
__device__ __forceinline__ void ldsm_x4_t(uint32_t* r, uint32_t a) {
    asm volatile("ldmatrix.sync.aligned.m8n8.x4.trans.shared.b16 {%0,%1,%2,%3}, [%4];"
                 : "=r"(r[0]), "=r"(r[1]), "=r"(r[2]), "=r"(r[3]) : "r"(a));
}
__device__ __forceinline__ void mma_f16(float* c, const uint32_t* a, const uint32_t* b) {
    asm volatile("mma.sync.aligned.m16n8k16.row.col.f32.f16.f16.f32 "
        "{%0,%1,%2,%3}, {%4,%5,%6,%7}, {%8,%9}, {%0,%1,%2,%3};"
        : "+f"(c[0]), "+f"(c[1]), "+f"(c[2]), "+f"(c[3])
        : "r"(a[0]), "r"(a[1]), "r"(a[2]), "r"(a[3]), "r"(b[0]), "r"(b[1]));
}
__device__ __forceinline__ uint2 cvt4h(float4 f) {
    __half2 h01 = __floats2half2_rn(f.x, f.y);
    __half2 h23 = __floats2half2_rn(f.z, f.w);
    return make_uint2(*(uint32_t*)&h01, *(uint32_t*)&h23);
}
#define CP_ASYNC16(dst, src) \
    asm volatile("cp.async.cg.shared.global [%0], [%1], 16;" \
                 :: "r"((uint32_t)(dst)), "l"(src))
#define CP_COMMIT() asm volatile("cp.async.commit_group;" ::: "memory")
#define CP_WAIT0()  asm volatile("cp.async.wait_group 0;" ::: "memory")

// per-CTA tile resolve: scan 33 experts (expert NE = shared, count T_TOK).
// returns false if tilei is beyond the live tile count.
__device__ __forceinline__ bool resolve_tile(int tilei, int& e, int& s0,
                                             int& rows, int& hidbase) {
    int acc = 0, off = 0;
    e = -1;
    #pragma unroll 1
    for (int ee = 0; ee < NE_TOT; ee++) {
        int c = (ee < NE) ? g_cnt[ee] : T_TOK;
        int nt = (c + BM - 1) / BM;
        if (e < 0 && tilei < acc + nt) {
            e = ee;
            s0 = (tilei - acc) * BM;
            rows = min(BM, c - s0);
            hidbase = off + s0;
        }
        acc += nt; off += c;
    }
    return e >= 0;
}

// ===================== router (R14 form) + x->fp16 plane =====================
__global__ void __launch_bounds__(256)
router_kernel(const float* __restrict__ x,
              const float* __restrict__ rw,
              const float* __restrict__ bias) {
    __shared__ float rwS[32][65];
    __shared__ float xS[8][64];
    int warp = threadIdx.x >> 5, lane = threadIdx.x & 31;
    int t = blockIdx.x * 8 + warp;

    float acc = 0.f;
    for (int h0 = 0; h0 < HID; h0 += 64) {
        __syncthreads();
        for (int i = threadIdx.x; i < 32 * 64; i += 256) {
            int e = i >> 6, j = i & 63;
            rwS[e][j] = rw[e * HID + h0 + j];
        }
        float x0 = x[(size_t)t * HID + h0 + lane];
        float x1 = x[(size_t)t * HID + h0 + 32 + lane];
        xS[warp][lane]      = x0;
        xS[warp][lane + 32] = x1;
        g_xhi[(size_t)t * HID + h0 + lane]      = __float2half_rn(x0);
        g_xhi[(size_t)t * HID + h0 + 32 + lane] = __float2half_rn(x1);
        __syncthreads();
        #pragma unroll 8
        for (int j = 0; j < 64; j++)
            acc += xS[warp][j] * rwS[lane][j];
    }
    float score = 1.f / (1.f + __expf(-acc));
    float selv  = score + bias[lane];

    int   picks[TOPK];
    float pw[TOPK];
    float wsum = 0.f;
    #pragma unroll
    for (int k = 0; k < TOPK; k++) {
        float v = selv; int idx = lane;
        #pragma unroll
        for (int o = 16; o > 0; o >>= 1) {
            float v2 = __shfl_xor_sync(0xFFFFFFFFu, v, o);
            int   i2 = __shfl_xor_sync(0xFFFFFFFFu, idx, o);
            if (v2 > v || (v2 == v && i2 < idx)) { v = v2; idx = i2; }
        }
        picks[k] = idx;
        float w = __shfl_sync(0xFFFFFFFFu, score, idx);
        pw[k] = w; wsum += w;
        if (lane == idx) selv = -INFINITY;
    }
    if (lane == 0) {
        float inv = 1.f / (wsum + 1e-20f);
        #pragma unroll
        for (int k = 0; k < TOPK; k++) {
            int e = picks[k];
            int pos = atomicAdd(&g_cnt[e], 1);
            g_tok[e * T_TOK + pos] = t;
            g_w  [e * T_TOK + pos] = pw[k] * inv;
        }
        g_tok[NE * T_TOK + t] = t;   // shared expert identity routing
        g_w  [NE * T_TOK + t] = 1.0f;
    }
}

// ===================== gate+up GEMM, fp16 single-pass, occ 2 =====================
// CTA: M128 x N64 (gate AND up). A via cp.async (fp16 plane); B inline LDG->cvt->STS.
// stage 32KB: A 16KB ; Bg 8KB | Bu 8KB.
#define GU_SMEM (1024 + 2 * 32768)
__global__ void __launch_bounds__(256, 2)
gu_gemm(const float* __restrict__ wgR, const float* __restrict__ wuR,
        const float* __restrict__ wgS, const float* __restrict__ wuS) {
    extern __shared__ char sm[];
    uint32_t sa = smem_u32(sm);
    int* rowTokS = (int*)sm;

    int e, s0, rows, hidbase;
    if (!resolve_tile(blockIdx.y, e, s0, rows, hidbase)) return;
    int N0 = blockIdx.x * 64;

    int tid = threadIdx.x, lane = tid & 31, wid = tid >> 5;
    int wm = wid & 3, wn = wid >> 2;

    if (tid < 128)
        rowTokS[tid] = g_tok[e * T_TOK + s0 + min(tid, rows - 1)];
    __syncthreads();

    const float* gptr = (e < NE) ? wgR + (size_t)e * HID * INTD : wgS;
    const float* uptr = (e < NE) ? wuR + (size_t)e * HID * INTD : wuS;

    int aJ = tid & 7;
    int tokR[4];
    uint32_t aDst[4];
    #pragma unroll
    for (int i = 0; i < 4; i++) {
        int r = (tid >> 3) + 32 * i;
        tokR[i] = rowTokS[r];
        aDst[i] = r * 128 + ((aJ * 16) ^ ((r & 7) << 4));
    }
    int bK = tid >> 2, bC = (tid & 3) * 4;

    {
        uint32_t As0 = sa + 1024;
        #pragma unroll
        for (int i = 0; i < 4; i++)
            CP_ASYNC16(As0 + aDst[i], &g_xhi[(size_t)tokR[i] * HID + aJ * 8]);
        CP_COMMIT();
    }

    float accG[2][4][4], accU[2][4][4];
    #pragma unroll
    for (int a = 0; a < 2; a++)
        #pragma unroll
        for (int b = 0; b < 4; b++)
            #pragma unroll
            for (int f = 0; f < 4; f++) { accG[a][b][f] = 0.f; accU[a][b][f] = 0.f; }

    const int KCH = HID / 64;
    int lm = lane & 15, lkh = lane >> 4;
    int swb = (bK & 7) << 4;

    for (int c = 0; c < KCH; c++) {
        uint32_t As = sa + 1024 + (c & 1) * 32768;
        uint32_t Bg = As + 16384;
        char* Bsm = sm + 1024 + (c & 1) * 32768 + 16384;
        int k0 = c * 64;

        CP_WAIT0();
        #pragma unroll
        for (int j = 0; j < 4; j++) {
            float4 g4 = *(const float4*)&gptr[(size_t)(k0 + bK) * INTD + N0 + bC + 16 * j];
            float4 u4 = *(const float4*)&uptr[(size_t)(k0 + bK) * INTD + N0 + bC + 16 * j];
            int nb = (bC + 16 * j) * 2;
            *(uint2*)(Bsm +        bK * 128 + (nb ^ swb)) = cvt4h(g4);
            *(uint2*)(Bsm + 8192 + bK * 128 + (nb ^ swb)) = cvt4h(u4);
        }
        __syncthreads();

        if (c + 1 < KCH) {
            int kn = (c + 1) * 64;
            uint32_t Asn = sa + 1024 + ((c + 1) & 1) * 32768;
            #pragma unroll
            for (int i = 0; i < 4; i++)
                CP_ASYNC16(Asn + aDst[i], &g_xhi[(size_t)tokR[i] * HID + kn + aJ * 8]);
            CP_COMMIT();
        }

        #pragma unroll
        for (int ks = 0; ks < 4; ks++) {
            uint32_t Gh[2][4], Uh[2][4];
            #pragma unroll
            for (int pr = 0; pr < 2; pr++) {
                int k = ks * 16 + lm;
                int n = wn * 32 + pr * 16 + lkh * 8;
                uint32_t ad = Bg + k * 128 + ((n * 2) ^ ((k & 7) << 4));
                ldsm_x4_t(Gh[pr], ad);
                ldsm_x4_t(Uh[pr], ad + 8192);
            }
            #pragma unroll
            for (int mt = 0; mt < 2; mt++) {
                int m = wm * 32 + mt * 16 + lm;
                int boff = (lkh * 16 + ks * 32) ^ ((m & 7) << 4);
                uint32_t Ah[4];
                ldsm_x4(Ah, As + m * 128 + boff);
                #pragma unroll
                for (int nt = 0; nt < 4; nt++) {
                    mma_f16(accG[mt][nt], Ah, &Gh[nt >> 1][(nt & 1) * 2]);
                    mma_f16(accU[mt][nt], Ah, &Uh[nt >> 1][(nt & 1) * 2]);
                }
            }
        }
    }

    int gr = lane >> 2, gc = (lane & 3) * 2;
    #pragma unroll
    for (int mt = 0; mt < 2; mt++) {
        #pragma unroll
        for (int nt = 0; nt < 4; nt++) {
            int col = N0 + wn * 32 + nt * 8 + gc;
            #pragma unroll
            for (int p = 0; p < 2; p++) {
                int r = wm * 32 + mt * 16 + gr + p * 8;
                if (r < rows) {
                    float g0 = accG[mt][nt][2 * p], g1 = accG[mt][nt][2 * p + 1];
                    float u0 = accU[mt][nt][2 * p], u1 = accU[mt][nt][2 * p + 1];
                    float h0 = (g0 / (1.f + __expf(-g0))) * u0;
                    float h1 = (g1 / (1.f + __expf(-g1))) * u1;
                    __half2 hh(__float2half_rn(h0), __float2half_rn(h1));
                    size_t o = (size_t)(hidbase + r) * INTD + col;
                    *(uint32_t*)&g_hhi[o] = *(uint32_t*)&hh;
                }
            }
        }
    }
}

// ===================== down GEMM, fp16 single-pass, occ 2 + scatter =====================
#define DN_SMEM (1024 + 2 * 32768)
__global__ void __launch_bounds__(256, 2)
dn_gemm(const float* __restrict__ wdR, const float* __restrict__ wdS,
        float* __restrict__ out) {
    extern __shared__ char sm[];
    uint32_t sa = smem_u32(sm);
    int* rowTokS = (int*)sm;
    float* rowWS = (float*)(sm + 512);

    int e, s0, rows, hidbase;
    if (!resolve_tile(blockIdx.y, e, s0, rows, hidbase)) return;
    int N0 = blockIdx.x * 128;

    int tid = threadIdx.x, lane = tid & 31, wid = tid >> 5;
    int wm = wid & 3, wn = wid >> 2;

    if (tid < 128) {
        int idx = e * T_TOK + s0 + min(tid, rows - 1);
        rowTokS[tid] = g_tok[idx];
        rowWS[tid]   = g_w[idx];
    }
    __syncthreads();

    const float* wd = (e < NE) ? wdR + (size_t)e * INTD * HID : wdS;

    int aJ = tid & 7;
    int arR[4];
    uint32_t aDst[4];
    #pragma unroll
    for (int i = 0; i < 4; i++) {
        int r = (tid >> 3) + 32 * i;
        arR[i] = hidbase + min(r, rows - 1);
        aDst[i] = r * 128 + ((aJ * 16) ^ ((r & 7) << 4));
    }
    int bK = tid >> 2, bC = (tid & 3) * 4;

    {
        uint32_t As0 = sa + 1024;
        #pragma unroll
        for (int i = 0; i < 4; i++)
            CP_ASYNC16(As0 + aDst[i], &g_hhi[(size_t)arR[i] * INTD + aJ * 8]);
        CP_COMMIT();
    }

    float acc[2][8][4];
    #pragma unroll
    for (int a = 0; a < 2; a++)
        #pragma unroll
        for (int b = 0; b < 8; b++)
            #pragma unroll
            for (int f = 0; f < 4; f++) acc[a][b][f] = 0.f;

    const int KCH = INTD / 64;
    int lm = lane & 15, lkh = lane >> 4;
    int swb = (bK & 7) << 4;

    for (int c = 0; c < KCH; c++) {
        uint32_t As = sa + 1024 + (c & 1) * 32768;
        uint32_t Bs = As + 16384;
        char* Bsm = sm + 1024 + (c & 1) * 32768 + 16384;
        int k0 = c * 64;

        CP_WAIT0();
        #pragma unroll
        for (int j = 0; j < 8; j++) {
            float4 b4 = *(const float4*)&wd[(size_t)(k0 + bK) * HID + N0 + bC + 16 * j];
            int nb = (bC + 16 * j) * 2;
            *(uint2*)(Bsm + bK * 256 + (nb ^ swb)) = cvt4h(b4);
        }
        __syncthreads();

        if (c + 1 < KCH) {
            int kn = (c + 1) * 64;
            uint32_t Asn = sa + 1024 + ((c + 1) & 1) * 32768;
            #pragma unroll
            for (int i = 0; i < 4; i++)
                CP_ASYNC16(Asn + aDst[i], &g_hhi[(size_t)arR[i] * INTD + kn + aJ * 8]);
            CP_COMMIT();
        }

        #pragma unroll
        for (int ks = 0; ks < 4; ks++) {
            uint32_t Bh[4][4];
            #pragma unroll
            for (int h = 0; h < 2; h++)
                #pragma unroll
                for (int pr = 0; pr < 2; pr++) {
                    int k = ks * 16 + lm;
                    int n = wn * 64 + h * 32 + pr * 16 + lkh * 8;
                    uint32_t ad = Bs + k * 256 + ((n * 2) ^ ((k & 7) << 4));
                    ldsm_x4_t(Bh[h * 2 + pr], ad);
                }
            #pragma unroll
            for (int mt = 0; mt < 2; mt++) {
                int m = wm * 32 + mt * 16 + lm;
                int boff = (lkh * 16 + ks * 32) ^ ((m & 7) << 4);
                uint32_t Ah[4];
                ldsm_x4(Ah, As + m * 128 + boff);
                #pragma unroll
                for (int nt = 0; nt < 8; nt++)
                    mma_f16(acc[mt][nt], Ah, &Bh[nt >> 1][(nt & 1) * 2]);
            }
        }
    }

    int gr = lane >> 2, gc = (lane & 3) * 2;
    #pragma unroll
    for (int mt = 0; mt < 2; mt++) {
        #pragma unroll
        for (int nt = 0; nt < 8; nt++) {
            int r0 = wm * 32 + mt * 16 + gr;
            int col = N0 + wn * 64 + nt * 8 + gc;
            if (r0 < rows) {
                int tok = rowTokS[r0]; float w = rowWS[r0];
                atomicAdd(&out[(size_t)tok * HID + col],     acc[mt][nt][0] * w);
                atomicAdd(&out[(size_t)tok * HID + col + 1], acc[mt][nt][1] * w);
            }
            if (r0 + 8 < rows) {
                int tok = rowTokS[r0 + 8]; float w = rowWS[r0 + 8];
                atomicAdd(&out[(size_t)tok * HID + col],     acc[mt][nt][2] * w);
                atomicAdd(&out[(size_t)tok * HID + col + 1], acc[mt][nt][3] * w);
            }
        }
    }
}

// ===================== launch =====================
extern "C" void kernel_launch(void* const* d_in, const int* in_sizes, int n_in,
                              void* d_out, int out_size) {
    const float* x    = (const float*)d_in[0];
    const float* rw   = (const float*)d_in[1];
    const float* bias = (const float*)d_in[2];
    const float* wg   = (const float*)d_in[3];
    const float* wu   = (const float*)d_in[4];
    const float* wd   = (const float*)d_in[5];
    const float* swg  = (const float*)d_in[6];
    const float* swu  = (const float*)d_in[7];
    const float* swd  = (const float*)d_in[8];
    float* out = (float*)d_out;

    cudaFuncSetAttribute(gu_gemm, cudaFuncAttributeMaxDynamicSharedMemorySize, GU_SMEM);
    cudaFuncSetAttribute(dn_gemm, cudaFuncAttributeMaxDynamicSharedMemorySize, DN_SMEM);

    void* cntAddr = nullptr;
    cudaGetSymbolAddress(&cntAddr, g_cnt);

    cudaMemsetAsync(d_out, 0, (size_t)out_size * sizeof(float));
    cudaMemsetAsync(cntAddr, 0, NE * sizeof(int));
    router_kernel<<<T_TOK / 8, 256>>>(x, rw, bias);

    gu_gemm<<<dim3(INTD / 64, MAXTILES), 256, GU_SMEM>>>(wg, wu, swg, swu);
    dn_gemm<<<dim3(HID / 128, MAXTILES), 256, DN_SMEM>>>(wd, swd, out);
}

// round 17
// speedup vs baseline: 1.1215x; 1.0797x over previous
#include <cuda_runtime.h>
#include <cuda_fp16.h>
#include <math.h>
#include <stdint.h>

#define T_TOK 2048
#define HID   2048
#define INTD  1024
#define NE    32
#define NE_TOT 33
#define TOPK  4
#define MAXTILES 112
#define BM    128
#define ROWS_MAX 10368

// ===================== device scratch =====================
__device__ int   g_cnt[NE];                 // memset to 0 each call
__device__ int   g_tok[NE_TOT * T_TOK];
__device__ float g_w  [NE_TOT * T_TOK];
__device__ int   g_off[NE_TOT + 1];
__device__ int   g_tile_e[MAXTILES];
__device__ int   g_tile_s[MAXTILES];
__device__ int   g_ntiles;
__device__ float g_part[2][T_TOK][NE];      // partial logits (H halves)
// x as single fp16 plane (written by router)
__device__ __align__(16) __half g_xhi[(size_t)T_TOK * HID];
// intermediate h = silu(g)*u, single fp16 plane
__device__ __align__(16) __half g_hhi[(size_t)ROWS_MAX * INTD];

// ===================== PTX helpers =====================
__device__ __forceinline__ uint32_t smem_u32(const void* p) {
    uint32_t a;
    asm("{ .reg .u64 t; cvta.to.shared.u64 t, %1; cvt.u32.u64 %0, t; }" : "=r"(a) : "l"(p));
    return a;
}
__device__ __forceinline__ void ldsm_x4(uint32_t* r, uint32_t a) {
    asm volatile("ldmatrix.sync.aligned.m8n8.x4.shared.b16 {%0,%1,%2,%3}, [%4];"
                 : "=r"(r[0]), "=r"(r[1]), "=r"(r[2]), "=r"(r[3]) : "r"(a));
}
__device__ __forceinline__ void ldsm_x4_t(uint32_t* r, uint32_t a) {
    asm volatile("ldmatrix.sync.aligned.m8n8.x4.trans.shared.b16 {%0,%1,%2,%3}, [%4];"
                 : "=r"(r[0]), "=r"(r[1]), "=r"(r[2]), "=r"(r[3]) : "r"(a));
}
__device__ __forceinline__ void mma_f16(float* c, const uint32_t* a, const uint32_t* b) {
    asm volatile("mma.sync.aligned.m16n8k16.row.col.f32.f16.f16.f32 "
        "{%0,%1,%2,%3}, {%4,%5,%6,%7}, {%8,%9}, {%0,%1,%2,%3};"
        : "+f"(c[0]), "+f"(c[1]), "+f"(c[2]), "+f"(c[3])
        : "r"(a[0]), "r"(a[1]), "r"(a[2]), "r"(a[3]), "r"(b[0]), "r"(b[1]));
}
__device__ __forceinline__ uint2 cvt4h(float4 f) {
    __half2 h01 = __floats2half2_rn(f.x, f.y);
    __half2 h23 = __floats2half2_rn(f.z, f.w);
    return make_uint2(*(uint32_t*)&h01, *(uint32_t*)&h23);
}
#define CP_ASYNC16(dst, src) \
    asm volatile("cp.async.cg.shared.global [%0], [%1], 16;" \
                 :: "r"((uint32_t)(dst)), "l"(src))
#define CP_COMMIT() asm volatile("cp.async.commit_group;" ::: "memory")
#define CP_WAIT0()  asm volatile("cp.async.wait_group 0;" ::: "memory")

// ===================== router v3: partial logits over H-half =====================
// grid (T_TOK/8, 2); block 256. Each block: 8 tokens x 1024 H (16 chunks of 64).
__global__ void __launch_bounds__(256)
router_kernel(const float* __restrict__ x,
              const float* __restrict__ rw) {
    __shared__ float rwS[32][65];
    __shared__ float xS[8][64];
    int warp = threadIdx.x >> 5, lane = threadIdx.x & 31;
    int t = blockIdx.x * 8 + warp;
    int hbase = blockIdx.y * (HID / 2);

    float acc = 0.f;
    for (int hc = 0; hc < HID / 2; hc += 64) {
        int h0 = hbase + hc;
        __syncthreads();
        for (int i = threadIdx.x; i < 32 * 64; i += 256) {
            int e = i >> 6, j = i & 63;
            rwS[e][j] = rw[e * HID + h0 + j];
        }
        float x0 = x[(size_t)t * HID + h0 + lane];
        float x1 = x[(size_t)t * HID + h0 + 32 + lane];
        xS[warp][lane]      = x0;
        xS[warp][lane + 32] = x1;
        g_xhi[(size_t)t * HID + h0 + lane]      = __float2half_rn(x0);
        g_xhi[(size_t)t * HID + h0 + 32 + lane] = __float2half_rn(x1);
        __syncthreads();
        #pragma unroll 8
        for (int j = 0; j < 64; j++)
            acc += xS[warp][j] * rwS[lane][j];
    }
    g_part[blockIdx.y][t][lane] = acc;
}

// top-4 + list build. grid T_TOK/8; warp per token.
__global__ void __launch_bounds__(256)
topk_kernel(const float* __restrict__ bias) {
    int warp = threadIdx.x >> 5, lane = threadIdx.x & 31;
    int t = blockIdx.x * 8 + warp;

    float logit = g_part[0][t][lane] + g_part[1][t][lane];
    float score = 1.f / (1.f + __expf(-logit));
    float selv  = score + bias[lane];

    int   picks[TOPK];
    float pw[TOPK];
    float wsum = 0.f;
    #pragma unroll
    for (int k = 0; k < TOPK; k++) {
        float v = selv; int idx = lane;
        #pragma unroll
        for (int o = 16; o > 0; o >>= 1) {
            float v2 = __shfl_xor_sync(0xFFFFFFFFu, v, o);
            int   i2 = __shfl_xor_sync(0xFFFFFFFFu, idx, o);
            if (v2 > v || (v2 == v && i2 < idx)) { v = v2; idx = i2; }
        }
        picks[k] = idx;
        float w = __shfl_sync(0xFFFFFFFFu, score, idx);
        pw[k] = w; wsum += w;
        if (lane == idx) selv = -INFINITY;
    }
    if (lane == 0) {
        float inv = 1.f / (wsum + 1e-20f);
        #pragma unroll
        for (int k = 0; k < TOPK; k++) {
            int e = picks[k];
            int pos = atomicAdd(&g_cnt[e], 1);
            g_tok[e * T_TOK + pos] = t;
            g_w  [e * T_TOK + pos] = pw[k] * inv;
        }
        g_tok[NE * T_TOK + t] = t;
        g_w  [NE * T_TOK + t] = 1.0f;
    }
}

__global__ void build_tiles_kernel() {
    if (threadIdx.x == 0 && blockIdx.x == 0) {
        int off = 0, nt = 0;
        for (int e = 0; e < NE_TOT; e++) {
            g_off[e] = off;
            int c = (e < NE) ? g_cnt[e] : T_TOK;
            for (int s = 0; s < c && nt < MAXTILES; s += BM) {
                g_tile_e[nt] = e; g_tile_s[nt] = s; nt++;
            }
            off += c;
        }
        g_off[NE_TOT] = off;
        g_ntiles = nt;
    }
}

// ===================== gate+up GEMM, fp16 single-pass, occ 2 =====================
#define GU_SMEM (1024 + 2 * 32768)
__global__ void __launch_bounds__(256, 2)
gu_gemm(const float* __restrict__ wgR, const float* __restrict__ wuR,
        const float* __restrict__ wgS, const float* __restrict__ wuS) {
    extern __shared__ char sm[];
    uint32_t sa = smem_u32(sm);
    int* rowTokS = (int*)sm;

    int tilei = blockIdx.y;
    if (tilei >= g_ntiles) return;
    int e = g_tile_e[tilei], s0 = g_tile_s[tilei];
    int cnt = (e < NE) ? g_cnt[e] : T_TOK;
    int rows = min(BM, cnt - s0);
    int hidbase = g_off[e] + s0;
    int N0 = blockIdx.x * 64;

    int tid = threadIdx.x, lane = tid & 31, wid = tid >> 5;
    int wm = wid & 3, wn = wid >> 2;

    if (tid < 128)
        rowTokS[tid] = g_tok[e * T_TOK + s0 + min(tid, rows - 1)];
    __syncthreads();

    const float* gptr = (e < NE) ? wgR + (size_t)e * HID * INTD : wgS;
    const float* uptr = (e < NE) ? wuR + (size_t)e * HID * INTD : wuS;

    int aJ = tid & 7;
    int tokR[4];
    uint32_t aDst[4];
    #pragma unroll
    for (int i = 0; i < 4; i++) {
        int r = (tid >> 3) + 32 * i;
        tokR[i] = rowTokS[r];
        aDst[i] = r * 128 + ((aJ * 16) ^ ((r & 7) << 4));
    }
    int bK = tid >> 2, bC = (tid & 3) * 4;

    {
        uint32_t As0 = sa + 1024;
        #pragma unroll
        for (int i = 0; i < 4; i++)
            CP_ASYNC16(As0 + aDst[i], &g_xhi[(size_t)tokR[i] * HID + aJ * 8]);
        CP_COMMIT();
    }

    float accG[2][4][4], accU[2][4][4];
    #pragma unroll
    for (int a = 0; a < 2; a++)
        #pragma unroll
        for (int b = 0; b < 4; b++)
            #pragma unroll
            for (int f = 0; f < 4; f++) { accG[a][b][f] = 0.f; accU[a][b][f] = 0.f; }

    const int KCH = HID / 64;
    int lm = lane & 15, lkh = lane >> 4;
    int swb = (bK & 7) << 4;

    for (int c = 0; c < KCH; c++) {
        uint32_t As = sa + 1024 + (c & 1) * 32768;
        uint32_t Bg = As + 16384;
        char* Bsm = sm + 1024 + (c & 1) * 32768 + 16384;
        int k0 = c * 64;

        CP_WAIT0();
        #pragma unroll
        for (int j = 0; j < 4; j++) {
            float4 g4 = *(const float4*)&gptr[(size_t)(k0 + bK) * INTD + N0 + bC + 16 * j];
            float4 u4 = *(const float4*)&uptr[(size_t)(k0 + bK) * INTD + N0 + bC + 16 * j];
            int nb = (bC + 16 * j) * 2;
            *(uint2*)(Bsm +        bK * 128 + (nb ^ swb)) = cvt4h(g4);
            *(uint2*)(Bsm + 8192 + bK * 128 + (nb ^ swb)) = cvt4h(u4);
        }
        __syncthreads();

        if (c + 1 < KCH) {
            int kn = (c + 1) * 64;
            uint32_t Asn = sa + 1024 + ((c + 1) & 1) * 32768;
            #pragma unroll
            for (int i = 0; i < 4; i++)
                CP_ASYNC16(Asn + aDst[i], &g_xhi[(size_t)tokR[i] * HID + kn + aJ * 8]);
            CP_COMMIT();
        }

        #pragma unroll
        for (int ks = 0; ks < 4; ks++) {
            uint32_t Gh[2][4], Uh[2][4];
            #pragma unroll
            for (int pr = 0; pr < 2; pr++) {
                int k = ks * 16 + lm;
                int n = wn * 32 + pr * 16 + lkh * 8;
                uint32_t ad = Bg + k * 128 + ((n * 2) ^ ((k & 7) << 4));
                ldsm_x4_t(Gh[pr], ad);
                ldsm_x4_t(Uh[pr], ad + 8192);
            }
            #pragma unroll
            for (int mt = 0; mt < 2; mt++) {
                int m = wm * 32 + mt * 16 + lm;
                int boff = (lkh * 16 + ks * 32) ^ ((m & 7) << 4);
                uint32_t Ah[4];
                ldsm_x4(Ah, As + m * 128 + boff);
                #pragma unroll
                for (int nt = 0; nt < 4; nt++) {
                    mma_f16(accG[mt][nt], Ah, &Gh[nt >> 1][(nt & 1) * 2]);
                    mma_f16(accU[mt][nt], Ah, &Uh[nt >> 1][(nt & 1) * 2]);
                }
            }
        }
    }

    int gr = lane >> 2, gc = (lane & 3) * 2;
    #pragma unroll
    for (int mt = 0; mt < 2; mt++) {
        #pragma unroll
        for (int nt = 0; nt < 4; nt++) {
            int col = N0 + wn * 32 + nt * 8 + gc;
            #pragma unroll
            for (int p = 0; p < 2; p++) {
                int r = wm * 32 + mt * 16 + gr + p * 8;
                if (r < rows) {
                    float g0 = accG[mt][nt][2 * p], g1 = accG[mt][nt][2 * p + 1];
                    float u0 = accU[mt][nt][2 * p], u1 = accU[mt][nt][2 * p + 1];
                    float h0 = (g0 / (1.f + __expf(-g0))) * u0;
                    float h1 = (g1 / (1.f + __expf(-g1))) * u1;
                    __half2 hh(__float2half_rn(h0), __float2half_rn(h1));
                    size_t o = (size_t)(hidbase + r) * INTD + col;
                    *(uint32_t*)&g_hhi[o] = *(uint32_t*)&hh;
                }
            }
        }
    }
}

// ===================== down GEMM, fp16 single-pass, occ 2 + scatter =====================
#define DN_SMEM (1024 + 2 * 32768)
__global__ void __launch_bounds__(256, 2)
dn_gemm(const float* __restrict__ wdR, const float* __restrict__ wdS,
        float* __restrict__ out) {
    extern __shared__ char sm[];
    uint32_t sa = smem_u32(sm);
    int* rowTokS = (int*)sm;
    float* rowWS = (float*)(sm + 512);

    int tilei = blockIdx.y;
    if (tilei >= g_ntiles) return;
    int e = g_tile_e[tilei], s0 = g_tile_s[tilei];
    int cnt = (e < NE) ? g_cnt[e] : T_TOK;
    int rows = min(BM, cnt - s0);
    int hidbase = g_off[e] + s0;
    int N0 = blockIdx.x * 128;

    int tid = threadIdx.x, lane = tid & 31, wid = tid >> 5;
    int wm = wid & 3, wn = wid >> 2;

    if (tid < 128) {
        int idx = e * T_TOK + s0 + min(tid, rows - 1);
        rowTokS[tid] = g_tok[idx];
        rowWS[tid]   = g_w[idx];
    }
    __syncthreads();

    const float* wd = (e < NE) ? wdR + (size_t)e * INTD * HID : wdS;

    int aJ = tid & 7;
    int arR[4];
    uint32_t aDst[4];
    #pragma unroll
    for (int i = 0; i < 4; i++) {
        int r = (tid >> 3) + 32 * i;
        arR[i] = hidbase + min(r, rows - 1);
        aDst[i] = r * 128 + ((aJ * 16) ^ ((r & 7) << 4));
    }
    int bK = tid >> 2, bC = (tid & 3) * 4;

    {
        uint32_t As0 = sa + 1024;
        #pragma unroll
        for (int i = 0; i < 4; i++)
            CP_ASYNC16(As0 + aDst[i], &g_hhi[(size_t)arR[i] * INTD + aJ * 8]);
        CP_COMMIT();
    }

    float acc[2][8][4];
    #pragma unroll
    for (int a = 0; a < 2; a++)
        #pragma unroll
        for (int b = 0; b < 8; b++)
            #pragma unroll
            for (int f = 0; f < 4; f++) acc[a][b][f] = 0.f;

    const int KCH = INTD / 64;
    int lm = lane & 15, lkh = lane >> 4;
    int swb = (bK & 7) << 4;

    for (int c = 0; c < KCH; c++) {
        uint32_t As = sa + 1024 + (c & 1) * 32768;
        uint32_t Bs = As + 16384;
        char* Bsm = sm + 1024 + (c & 1) * 32768 + 16384;
        int k0 = c * 64;

        CP_WAIT0();
        #pragma unroll
        for (int j = 0; j < 8; j++) {
            float4 b4 = *(const float4*)&wd[(size_t)(k0 + bK) * HID + N0 + bC + 16 * j];
            int nb = (bC + 16 * j) * 2;
            *(uint2*)(Bsm + bK * 256 + (nb ^ swb)) = cvt4h(b4);
        }
        __syncthreads();

        if (c + 1 < KCH) {
            int kn = (c + 1) * 64;
            uint32_t Asn = sa + 1024 + ((c + 1) & 1) * 32768;
            #pragma unroll
            for (int i = 0; i < 4; i++)
                CP_ASYNC16(Asn + aDst[i], &g_hhi[(size_t)arR[i] * INTD + kn + aJ * 8]);
            CP_COMMIT();
        }

        #pragma unroll
        for (int ks = 0; ks < 4; ks++) {
            uint32_t Bh[4][4];
            #pragma unroll
            for (int h = 0; h < 2; h++)
                #pragma unroll
                for (int pr = 0; pr < 2; pr++) {
                    int k = ks * 16 + lm;
                    int n = wn * 64 + h * 32 + pr * 16 + lkh * 8;
                    uint32_t ad = Bs + k * 256 + ((n * 2) ^ ((k & 7) << 4));
                    ldsm_x4_t(Bh[h * 2 + pr], ad);
                }
            #pragma unroll
            for (int mt = 0; mt < 2; mt++) {
                int m = wm * 32 + mt * 16 + lm;
                int boff = (lkh * 16 + ks * 32) ^ ((m & 7) << 4);
                uint32_t Ah[4];
                ldsm_x4(Ah, As + m * 128 + boff);
                #pragma unroll
                for (int nt = 0; nt < 8; nt++)
                    mma_f16(acc[mt][nt], Ah, &Bh[nt >> 1][(nt & 1) * 2]);
            }
        }
    }

    int gr = lane >> 2, gc = (lane & 3) * 2;
    #pragma unroll
    for (int mt = 0; mt < 2; mt++) {
        #pragma unroll
        for (int nt = 0; nt < 8; nt++) {
            int r0 = wm * 32 + mt * 16 + gr;
            int col = N0 + wn * 64 + nt * 8 + gc;
            if (r0 < rows) {
                int tok = rowTokS[r0]; float w = rowWS[r0];
                atomicAdd(&out[(size_t)tok * HID + col],     acc[mt][nt][0] * w);
                atomicAdd(&out[(size_t)tok * HID + col + 1], acc[mt][nt][1] * w);
            }
            if (r0 + 8 < rows) {
                int tok = rowTokS[r0 + 8]; float w = rowWS[r0 + 8];
                atomicAdd(&out[(size_t)tok * HID + col],     acc[mt][nt][2] * w);
                atomicAdd(&out[(size_t)tok * HID + col + 1], acc[mt][nt][3] * w);
            }
        }
    }
}

// ===================== launch =====================
extern "C" void kernel_launch(void* const* d_in, const int* in_sizes, int n_in,
                              void* d_out, int out_size) {
    const float* x    = (const float*)d_in[0];
    const float* rw   = (const float*)d_in[1];
    const float* bias = (const float*)d_in[2];
    const float* wg   = (const float*)d_in[3];
    const float* wu   = (const float*)d_in[4];
    const float* wd   = (const float*)d_in[5];
    const float* swg  = (const float*)d_in[6];
    const float* swu  = (const float*)d_in[7];
    const float* swd  = (const float*)d_in[8];
    float* out = (float*)d_out;

    cudaFuncSetAttribute(gu_gemm, cudaFuncAttributeMaxDynamicSharedMemorySize, GU_SMEM);
    cudaFuncSetAttribute(dn_gemm, cudaFuncAttributeMaxDynamicSharedMemorySize, DN_SMEM);

    void* cntAddr = nullptr;
    cudaGetSymbolAddress(&cntAddr, g_cnt);

    cudaMemsetAsync(d_out, 0, (size_t)out_size * sizeof(float));
    cudaMemsetAsync(cntAddr, 0, NE * sizeof(int));

    router_kernel<<<dim3(T_TOK / 8, 2), 256>>>(x, rw);
    topk_kernel<<<T_TOK / 8, 256>>>(bias);
    build_tiles_kernel<<<1, 32>>>();

    gu_gemm<<<dim3(INTD / 64, MAXTILES), 256, GU_SMEM>>>(wg, wu, swg, swu);
    dn_gemm<<<dim3(HID / 128, MAXTILES), 256, DN_SMEM>>>(wd, swd, out);
}